// round 4
// baseline (speedup 1.0000x reference)
#include <cuda_runtime.h>
#include <cstddef>
#include <cstdint>

// Layout constants
#define DS      36          // padded row stride (floats): 16B-aligned float4/ulonglong2 access
#define NCHUNK  296         // 2 blocks per SM on 148 SMs
#define LVL1    37          // 296 / 8
#define LVL2    5           // ceil(37/8)
#define NTHR    160         // 128 compute threads (4 warps) + 32 bias threads

// Scratch (allocation-free: __device__ globals). Items stored as 32 rows x DS floats;
// cols 0..31 = matrix, col 32 = bias, cols 33..35 = padding (never read).
__device__ float g_it0[NCHUNK * 32 * DS];
__device__ float g_it1[LVL1 * 32 * DS];
__device__ float g_it2[LVL2 * 32 * DS];
__device__ float g_fin[32 * DS];
__device__ float g_P[2048 * 32];
__device__ int   g_flag;

typedef unsigned long long u64;

// Splat one f32 into both lanes of a packed f32x2.
__device__ __forceinline__ u64 pack2(float x) {
    u64 r; unsigned int xi = __float_as_uint(x);
    asm("mov.b64 %0, {%1, %1};" : "=l"(r) : "r"(xi));
    return r;
}
// d.lo += a.lo*b.lo ; d.hi += a.hi*b.hi   (one FMA-pipe slot, 2 MACs)
__device__ __forceinline__ void fma2(u64& d, u64 a, u64 b) {
    asm("fma.rn.f32x2 %0, %1, %2, %0;" : "+l"(d) : "l"(a), "l"(b));
}

// One affine composition step using packed f32x2:
//   Uo[c][j]  = sum_k Wb[c][k] * U[k][j]              (matrix, j = 0..31)
//   Uo[c][32] = sum_k Wb[c][k] * U[k][32] + Wb[c][32] (bias column)
// Threads 0..127: (c = t>>2, j0 = (t&3)*8) -> 8 output columns as 4 f32x2 accums.
// Threads 128..159: bias lane cc = t-128.
__device__ __forceinline__ void affine2(
    const float (*U)[DS], const float (*Wb)[DS], float (*Uo)[DS], int t)
{
    if (t < 128) {
        const int c  = t >> 2;
        const int j0 = (t & 3) * 8;
        float lrow[32];
#pragma unroll
        for (int q = 0; q < 8; ++q) {
            float4 v4 = *(const float4*)&Wb[c][4 * q];
            lrow[4 * q + 0] = v4.x; lrow[4 * q + 1] = v4.y;
            lrow[4 * q + 2] = v4.z; lrow[4 * q + 3] = v4.w;
        }
        u64 a0 = 0ull, a1 = 0ull, a2 = 0ull, a3 = 0ull;
#pragma unroll
        for (int k = 0; k < 32; ++k) {
            u64 lk = pack2(lrow[k]);
            ulonglong2 u01 = *(const ulonglong2*)&U[k][j0];
            ulonglong2 u23 = *(const ulonglong2*)&U[k][j0 + 4];
            fma2(a0, lk, u01.x);
            fma2(a1, lk, u01.y);
            fma2(a2, lk, u23.x);
            fma2(a3, lk, u23.y);
        }
        ulonglong2 r0; r0.x = a0; r0.y = a1;
        ulonglong2 r1; r1.x = a2; r1.y = a3;
        *(ulonglong2*)&Uo[c][j0]     = r0;
        *(ulonglong2*)&Uo[c][j0 + 4] = r1;
    } else {
        const int cc = t - 128;
        float lrow[32];
#pragma unroll
        for (int q = 0; q < 8; ++q) {  // conflict-free LDS.128 row reads
            float4 v4 = *(const float4*)&Wb[cc][4 * q];
            lrow[4 * q + 0] = v4.x; lrow[4 * q + 1] = v4.y;
            lrow[4 * q + 2] = v4.z; lrow[4 * q + 3] = v4.w;
        }
        float acc = Wb[cc][32];
#pragma unroll
        for (int k = 0; k < 32; ++k)
            acc = fmaf(lrow[k], U[k][32], acc);  // U[k][32]: broadcast read
        Uo[cc][32] = acc;
    }
}

// Stage 1: each block composes a contiguous chunk of layers sequentially.
__global__ __launch_bounds__(NTHR) void k_chunk(
    const float* __restrict__ W, const float* __restrict__ b,
    float* __restrict__ out)
{
    __shared__ float sU[2][32][DS];
    __shared__ float sW[2][32][DS];
    const int t   = threadIdx.x;
    const int blk = blockIdx.x;
    // 10000 = 232*34 + 64*33
    const int start = blk * 33 + (blk < 232 ? blk : 232);
    const int len   = 33 + (blk < 232 ? 1 : 0);
    const int end   = start + len;

    // U := identity (incl. zero bias col & padding)
    for (int idx = t; idx < 32 * DS; idx += NTHR) {
        int r = idx / DS, q = idx % DS;
        sU[0][r][q] = (q == r) ? 1.0f : 0.0f;
        sU[1][r][q] = 0.0f;
    }

    // Prefetch first layer into registers.
    // Compute thread t holds W[i] elements [t*8 .. t*8+7] (row c=t>>2, cols j0..j0+7).
    float4 w0 = make_float4(0,0,0,0), w1 = make_float4(0,0,0,0);
    float  breg = 0.f;
    if (t < 128) {
        const float* p = W + (size_t)start * 1024 + t * 8;
        w0 = *(const float4*)p; w1 = *(const float4*)(p + 4);
    } else {
        breg = b[start * 32 + (t - 128)];
    }
    const int c  = (t < 128) ? (t >> 2) : (t - 128);
    const int j0 = (t & 3) * 8;

    int p = 0;
    for (int i = start; i < end; ++i, p ^= 1) {
        if (t < 128) {
            *(float4*)&sW[p][c][j0]     = w0;
            *(float4*)&sW[p][c][j0 + 4] = w1;
        } else {
            sW[p][c][32] = breg;
        }
        __syncthreads();   // single barrier per layer (double-buffered)
        if (i + 1 < end) { // prefetch next layer during compute
            if (t < 128) {
                const float* pp = W + (size_t)(i + 1) * 1024 + t * 8;
                w0 = *(const float4*)pp; w1 = *(const float4*)(pp + 4);
            } else {
                breg = b[(i + 1) * 32 + (t - 128)];
            }
        }
        affine2(sU[p], sW[p], sU[p ^ 1], t);
    }
    __syncthreads();

    float* dst = out + (size_t)blk * (32 * DS);
    for (int idx = t; idx < 32 * DS; idx += NTHR)
        dst[idx] = sU[p][idx / DS][idx % DS];
}

// Tree combine: each block sequentially composes `group` consecutive items
// (earliest first). Item q acts as the "later" operand Wb.
__global__ __launch_bounds__(NTHR) void k_combine(
    const float* __restrict__ in, float* __restrict__ out,
    int group, int total, int resetFlag)
{
    __shared__ float sU[2][32][DS];
    __shared__ float sW[2][32][DS];
    const int t   = threadIdx.x;
    const int blk = blockIdx.x;
    const int startItem = blk * group;
    const int n = min(group, total - startItem);

    if (resetFlag && blk == 0 && t == 0) g_flag = 0;

    const float* first = in + (size_t)startItem * (32 * DS);
    for (int idx = t; idx < 32 * DS; idx += NTHR)
        sU[0][idx / DS][idx % DS] = first[idx];

    const int c  = (t < 128) ? (t >> 2) : (t - 128);
    const int j0 = (t & 3) * 8;

    float4 w0 = make_float4(0,0,0,0), w1 = make_float4(0,0,0,0);
    float  breg = 0.f;
    if (n > 1) {
        const float* it = in + (size_t)(startItem + 1) * (32 * DS);
        if (t < 128) {
            w0 = *(const float4*)&it[c * DS + j0];
            w1 = *(const float4*)&it[c * DS + j0 + 4];
        } else {
            breg = it[c * DS + 32];
        }
    }

    int p = 0;
    for (int q = 1; q < n; ++q, p ^= 1) {
        if (t < 128) {
            *(float4*)&sW[p][c][j0]     = w0;
            *(float4*)&sW[p][c][j0 + 4] = w1;
        } else {
            sW[p][c][32] = breg;
        }
        __syncthreads();
        if (q + 1 < n) {
            const float* it = in + (size_t)(startItem + q + 1) * (32 * DS);
            if (t < 128) {
                w0 = *(const float4*)&it[c * DS + j0];
                w1 = *(const float4*)&it[c * DS + j0 + 4];
            } else {
                breg = it[c * DS + 32];
            }
        }
        affine2(sU[p], sW[p], sU[p ^ 1], t);
    }
    __syncthreads();

    float* dst = out + (size_t)blk * (32 * DS);
    for (int idx = t; idx < 32 * DS; idx += NTHR)
        dst[idx] = sU[p][idx / DS][idx % DS];
}

// P = (y+z) @ M with M[k][d] = U[d][k]. Sets g_flag iff any P entry != 0.
__global__ void k_P(const float* __restrict__ y, const float* __restrict__ z)
{
    __shared__ float shU[32 * DS];
    const int t = threadIdx.x;
    for (int idx = t; idx < 32 * DS; idx += 256) shU[idx] = g_fin[idx];
    __syncthreads();

    const int gid = blockIdx.x * 256 + t;   // 2048*32 outputs
    const int e = gid >> 5, d = gid & 31;
    const float* yr = y + e * 32;
    const float* zr = z + e * 32;
    float acc = 0.f;
#pragma unroll
    for (int m = 0; m < 32; ++m)
        acc = fmaf(yr[m] + zr[m], shU[d * DS + m], acc);
    g_P[gid] = acc;
    if (acc != 0.0f) atomicOr(&g_flag, 1);
}

// out[row][d] = v[d]                          if P == 0 exactly (bit-equal fast path)
//             = sum_m x[row][m]*P[m][d]+v[d]  otherwise
__global__ void k_out(const float* __restrict__ x, float* __restrict__ out)
{
    __shared__ float shv[32];
    __shared__ int   sflag;
    const int t = threadIdx.x;
    if (t < 32) shv[t] = g_fin[t * DS + 32];
    if (t == 0) sflag = g_flag;
    __syncthreads();

    const int gid = blockIdx.x * 256 + t;   // 1024*32 outputs
    const int row = gid >> 5, d = gid & 31;
    if (!sflag) { out[gid] = shv[d]; return; }

    const float* xr = x + (size_t)row * 2048;
    float acc = shv[d];
#pragma unroll 4
    for (int m = 0; m < 2048; m += 4) {
        float4 xv = *(const float4*)(xr + m);
        acc = fmaf(xv.x, g_P[(m + 0) * 32 + d], acc);
        acc = fmaf(xv.y, g_P[(m + 1) * 32 + d], acc);
        acc = fmaf(xv.z, g_P[(m + 2) * 32 + d], acc);
        acc = fmaf(xv.w, g_P[(m + 3) * 32 + d], acc);
    }
    out[gid] = acc;
}

extern "C" void kernel_launch(void* const* d_in, const int* in_sizes, int n_in,
                              void* d_out, int out_size)
{
    // Bind inputs by element count:
    //  x: 1024*2048, y/z: 65536 (symmetric: only y+z used),
    //  W: 10000*32*32, b: 10000*32
    const float *x = nullptr, *y = nullptr, *z = nullptr, *W = nullptr, *b = nullptr;
    for (int i = 0; i < n_in; ++i) {
        const float* p = (const float*)d_in[i];
        switch (in_sizes[i]) {
            case 2097152:  x = p; break;
            case 10240000: W = p; break;
            case 320000:   b = p; break;
            case 65536:    if (!y) y = p; else z = p; break;
            default: break;
        }
    }
    float* out = (float*)d_out;

    float *it0, *it1, *it2, *fin;
    cudaGetSymbolAddress((void**)&it0, g_it0);
    cudaGetSymbolAddress((void**)&it1, g_it1);
    cudaGetSymbolAddress((void**)&it2, g_it2);
    cudaGetSymbolAddress((void**)&fin, g_fin);

    k_chunk  <<<NCHUNK, NTHR>>>(W, b, it0);
    k_combine<<<LVL1,   NTHR>>>(it0, it1, 8,    NCHUNK, 0);
    k_combine<<<LVL2,   NTHR>>>(it1, it2, 8,    LVL1,   0);
    k_combine<<<1,      NTHR>>>(it2, fin, LVL2, LVL2,   1);
    k_P      <<<256,    256>>>(y, z);
    k_out    <<<128,    256>>>(x, out);
}

// round 5
// speedup vs baseline: 1.0297x; 1.0297x over previous
#include <cuda_runtime.h>
#include <cstddef>
#include <cstdint>

// Layout constants
#define DS      36          // item row stride in floats (cols 0-31 matrix, 32 bias, 33-35 pad)
#define WS      33          // staged-W row stride (floats) -> conflict-free scalar LDS
#define NCHUNK  592         // 4 blocks per SM on 148 SMs
#define LVL1    74          // 592 / 8
#define LVL2    10          // ceil(74/8)
#define NTHR    64          // 2 warps: warp w owns output cols [16w, 16w+16)

// Scratch (allocation-free: __device__ globals)
__device__ float g_it0[NCHUNK * 32 * DS];
__device__ float g_it1[LVL1 * 32 * DS];
__device__ float g_it2[LVL2 * 32 * DS];
__device__ float g_fin[32 * DS];
__device__ float g_P[2048 * 32];
__device__ int   g_flag;

typedef unsigned long long u64;

__device__ __forceinline__ u64 pack2(float x) {
    u64 r; unsigned int xi = __float_as_uint(x);
    asm("mov.b64 %0, {%1, %1};" : "=l"(r) : "r"(xi));
    return r;
}
// d.lo += a.lo*b.lo ; d.hi += a.hi*b.hi  (one FMA-pipe slot, 2 MACs)
__device__ __forceinline__ void fma2(u64& d, u64 a, u64 b) {
    asm("fma.rn.f32x2 %0, %1, %2, %0;" : "+l"(d) : "l"(a), "l"(b));
}

// One affine composition step.
//   Uo[l][j]  = sum_k Wrow_l[k] * U[k][j]            (j in [16w, 16w+16))
//   Uo[l][32] = sum_k Wrow_l[k] * U[k][32] + bl      (warp 1 only)
// lane l = row; W row read from stride-33 shared (conflict-free scalar LDS);
// U rows read as 4 broadcast LDS.128 per k (uniform address across the warp).
__device__ __forceinline__ void affine_core(
    const float (*U)[DS], const float* __restrict__ sWmat, float bl,
    float (*Uo)[DS], int lane, int w)
{
    const float* wr_s = sWmat + lane * WS;
    float wr[32];
#pragma unroll
    for (int k = 0; k < 32; ++k) wr[k] = wr_s[k];

    const int j0 = w * 16;
    u64 a0 = 0, a1 = 0, a2 = 0, a3 = 0, a4 = 0, a5 = 0, a6 = 0, a7 = 0;
    float accb = bl;
#pragma unroll
    for (int k = 0; k < 32; ++k) {
        u64 wk = pack2(wr[k]);
        const ulonglong2* up = (const ulonglong2*)&U[k][j0];
        ulonglong2 u01 = up[0];
        ulonglong2 u23 = up[1];
        fma2(a0, wk, u01.x); fma2(a1, wk, u01.y);
        fma2(a2, wk, u23.x); fma2(a3, wk, u23.y);
        ulonglong2 u45 = up[2];
        ulonglong2 u67 = up[3];
        fma2(a4, wk, u45.x); fma2(a5, wk, u45.y);
        fma2(a6, wk, u67.x); fma2(a7, wk, u67.y);
        if (w == 1) accb = fmaf(wr[k], U[k][32], accb);
    }
    ulonglong2* op = (ulonglong2*)&Uo[lane][j0];
    ulonglong2 r;
    r.x = a0; r.y = a1; op[0] = r;
    r.x = a2; r.y = a3; op[1] = r;
    r.x = a4; r.y = a5; op[2] = r;
    r.x = a6; r.y = a7; op[3] = r;
    if (w == 1) Uo[lane][32] = accb;
}

// Stage 16 prefetched floats (4 float4) into stride-33 shared W.
// Thread t holds matrix floats [t*16, t*16+16): row c = t>>1, col base (t&1)*16.
// Scalar STS pattern (c + j) % 32 is conflict-free across the warp.
__device__ __forceinline__ void stage_W(float* sWmat, const float4* f, int t) {
    const int c  = t >> 1;
    const int jb = (t & 1) * 16;
    float* dst = sWmat + c * WS + jb;
#pragma unroll
    for (int q = 0; q < 4; ++q) {
        dst[q * 4 + 0] = f[q].x; dst[q * 4 + 1] = f[q].y;
        dst[q * 4 + 2] = f[q].z; dst[q * 4 + 3] = f[q].w;
    }
}

// Stage 1: each block composes a contiguous chunk of layers sequentially.
__global__ __launch_bounds__(NTHR) void k_chunk(
    const float* __restrict__ W, const float* __restrict__ b,
    float* __restrict__ out)
{
    __shared__ float sU[2][32][DS];
    __shared__ float sW[2][32 * WS];
    const int t    = threadIdx.x;
    const int lane = t & 31;
    const int w    = t >> 5;
    const int blk  = blockIdx.x;
    // 10000 = 528*17 + 64*16
    const int start = blk * 16 + (blk < 528 ? blk : 528);
    const int len   = 16 + (blk < 528 ? 1 : 0);
    const int end   = start + len;

    // U := identity, zero bias col
    for (int idx = t; idx < 32 * DS; idx += NTHR) {
        int r = idx / DS, q = idx % DS;
        sU[0][r][q] = (q == r) ? 1.0f : 0.0f;
    }

    // Prefetch first layer: thread t holds floats [t*16, t*16+16) of the 1024-float W layer.
    float4 f[4];
    {
        const float4* src = (const float4*)(W + (size_t)start * 1024 + t * 16);
#pragma unroll
        for (int q = 0; q < 4; ++q) f[q] = src[q];
    }
    float breg = (w == 1) ? b[start * 32 + lane] : 0.f;

    int p = 0;
    for (int i = start; i < end; ++i, p ^= 1) {
        stage_W(sW[p], f, t);
        float bl = breg;
        __syncthreads();                 // single barrier per layer (double-buffered)
        if (i + 1 < end) {               // prefetch next layer during compute
            const float4* src = (const float4*)(W + (size_t)(i + 1) * 1024 + t * 16);
#pragma unroll
            for (int q = 0; q < 4; ++q) f[q] = src[q];
            if (w == 1) breg = b[(i + 1) * 32 + lane];
        }
        affine_core(sU[p], sW[p], bl, sU[p ^ 1], lane, w);
    }
    __syncthreads();

    float* dst = out + (size_t)blk * (32 * DS);
    const float* srcU = &sU[p][0][0];
    for (int idx = t; idx < 32 * DS; idx += NTHR)
        dst[idx] = srcU[idx];
}

// Tree combine: each block composes `group` consecutive items (earliest first).
// Item q acts as the "later" operand (its matrix staged like W, bias read per-lane).
__global__ __launch_bounds__(NTHR) void k_combine(
    const float* __restrict__ in, float* __restrict__ out,
    int group, int total, int resetFlag)
{
    __shared__ float sU[2][32][DS];
    __shared__ float sW[2][32 * WS];
    const int t    = threadIdx.x;
    const int lane = t & 31;
    const int w    = t >> 5;
    const int blk  = blockIdx.x;
    const int startItem = blk * group;
    const int n = min(group, total - startItem);

    if (resetFlag && blk == 0 && t == 0) g_flag = 0;

    const float* first = in + (size_t)startItem * (32 * DS);
    for (int idx = t; idx < 32 * DS; idx += NTHR)
        (&sU[0][0][0])[idx] = first[idx];

    float4 f[4];
    float breg = 0.f;
    if (n > 1) {
        const float* it = in + (size_t)(startItem + 1) * (32 * DS);
        const float* rp = it + (t >> 1) * DS + (t & 1) * 16;
#pragma unroll
        for (int q = 0; q < 4; ++q) f[q] = *(const float4*)(rp + q * 4);
        if (w == 1) breg = it[lane * DS + 32];
    }

    int p = 0;
    for (int q = 1; q < n; ++q, p ^= 1) {
        stage_W(sW[p], f, t);
        float bl = breg;
        __syncthreads();
        if (q + 1 < n) {
            const float* it = in + (size_t)(startItem + q + 1) * (32 * DS);
            const float* rp = it + (t >> 1) * DS + (t & 1) * 16;
#pragma unroll
            for (int qq = 0; qq < 4; ++qq) f[qq] = *(const float4*)(rp + qq * 4);
            if (w == 1) breg = it[lane * DS + 32];
        }
        affine_core(sU[p], sW[p], bl, sU[p ^ 1], lane, w);
    }
    __syncthreads();

    float* dst = out + (size_t)blk * (32 * DS);
    const float* srcU = &sU[p][0][0];
    for (int idx = t; idx < 32 * DS; idx += NTHR)
        dst[idx] = srcU[idx];
}

// P = (y+z) @ M with M[k][d] = U[d][k]. Sets g_flag iff any P entry != 0.
__global__ void k_P(const float* __restrict__ y, const float* __restrict__ z)
{
    __shared__ float shU[32 * DS];
    const int t = threadIdx.x;
    for (int idx = t; idx < 32 * DS; idx += 256) shU[idx] = g_fin[idx];
    __syncthreads();

    const int gid = blockIdx.x * 256 + t;   // 2048*32 outputs
    const int e = gid >> 5, d = gid & 31;
    const float* yr = y + e * 32;
    const float* zr = z + e * 32;
    float acc = 0.f;
#pragma unroll
    for (int m = 0; m < 32; ++m)
        acc = fmaf(yr[m] + zr[m], shU[d * DS + m], acc);
    g_P[gid] = acc;
    if (acc != 0.0f) atomicOr(&g_flag, 1);
}

// out[row][d] = v[d]                          if P == 0 exactly (bit-equal fast path)
//             = sum_m x[row][m]*P[m][d]+v[d]  otherwise
__global__ void k_out(const float* __restrict__ x, float* __restrict__ out)
{
    __shared__ float shv[32];
    __shared__ int   sflag;
    const int t = threadIdx.x;
    if (t < 32) shv[t] = g_fin[t * DS + 32];
    if (t == 0) sflag = g_flag;
    __syncthreads();

    const int gid = blockIdx.x * 256 + t;   // 1024*32 outputs
    const int row = gid >> 5, d = gid & 31;
    if (!sflag) { out[gid] = shv[d]; return; }

    const float* xr = x + (size_t)row * 2048;
    float acc = shv[d];
#pragma unroll 4
    for (int m = 0; m < 2048; m += 4) {
        float4 xv = *(const float4*)(xr + m);
        acc = fmaf(xv.x, g_P[(m + 0) * 32 + d], acc);
        acc = fmaf(xv.y, g_P[(m + 1) * 32 + d], acc);
        acc = fmaf(xv.z, g_P[(m + 2) * 32 + d], acc);
        acc = fmaf(xv.w, g_P[(m + 3) * 32 + d], acc);
    }
    out[gid] = acc;
}

extern "C" void kernel_launch(void* const* d_in, const int* in_sizes, int n_in,
                              void* d_out, int out_size)
{
    // Bind inputs by element count:
    //  x: 1024*2048, y/z: 65536 (symmetric: only y+z used),
    //  W: 10000*32*32, b: 10000*32
    const float *x = nullptr, *y = nullptr, *z = nullptr, *W = nullptr, *b = nullptr;
    for (int i = 0; i < n_in; ++i) {
        const float* p = (const float*)d_in[i];
        switch (in_sizes[i]) {
            case 2097152:  x = p; break;
            case 10240000: W = p; break;
            case 320000:   b = p; break;
            case 65536:    if (!y) y = p; else z = p; break;
            default: break;
        }
    }
    float* out = (float*)d_out;

    float *it0, *it1, *it2, *fin;
    cudaGetSymbolAddress((void**)&it0, g_it0);
    cudaGetSymbolAddress((void**)&it1, g_it1);
    cudaGetSymbolAddress((void**)&it2, g_it2);
    cudaGetSymbolAddress((void**)&fin, g_fin);

    k_chunk  <<<NCHUNK, NTHR>>>(W, b, it0);
    k_combine<<<LVL1,   NTHR>>>(it0, it1, 8,    NCHUNK, 0);   // 592 -> 74
    k_combine<<<LVL2,   NTHR>>>(it1, it2, 8,    LVL1,   0);   // 74  -> 10
    k_combine<<<1,      NTHR>>>(it2, fin, LVL2, LVL2,   1);   // 10  -> 1
    k_P      <<<256,    256>>>(y, z);
    k_out    <<<128,    256>>>(x, out);
}